// round 16
// baseline (speedup 1.0000x reference)
#include <cuda_runtime.h>

typedef unsigned long long u64;
typedef unsigned int u32;

__device__ __forceinline__ u64 pack2(float x, float y) {
    u64 r; asm("mov.b64 %0, {%1, %2};" : "=l"(r) : "f"(x), "f"(y)); return r;
}
__device__ __forceinline__ u64 pack2dup(float x) {
    u64 r; asm("mov.b64 %0, {%1, %1};" : "=l"(r) : "f"(x)); return r;
}
__device__ __forceinline__ void unpack2(u64 v, float& x, float& y) {
    asm("mov.b64 {%0, %1}, %2;" : "=f"(x), "=f"(y) : "l"(v));
}
__device__ __forceinline__ u64 ffma2(u64 a, u64 b, u64 c) {
    u64 d; asm("fma.rn.f32x2 %0, %1, %2, %3;" : "=l"(d) : "l"(a), "l"(b), "l"(c));
    return d;
}

#define HS 36   // H row stride (16B-aligned rows)

// K1 pool layout (floats), 5632 total:
//  At8 (1024 u32) @0 | H0 @1024..3328 | H1 @3328..5632
#define P_H0   1024
#define P_H1   3328

#define MAXB 4096
__device__ float g_pool_scratch[MAXB * 320];   // [g][ci*10 + r]

// ---- agg: Z[n][c] = sum_k A[n][k]*H[k][c]; A byte-packed (incl. diag) ----
// Warp w owns nodes 16w..16w+15 (ALL channels). lane = (ni<<3)|ci:
// nodes n0 = 16w + 4*ni + g (uint4 A frag), channels c0 = ci*2*PP.
template<int W>
__device__ __forceinline__ void agg_frag(const u32* __restrict__ At8,
                                         const float* __restrict__ H,
                                         float* __restrict__ Z, int t)
{
    constexpr int PP = W / 16;          // 2 (W=32) or 1 (W=16)
    const int warp = t >> 5, lane = t & 31;
    const int ni = lane >> 3, ci = lane & 7;
    const int n0 = warp * 16 + 4 * ni;
    const int c0 = ci * 2 * PP;

    u64 acc[4][PP];
    #pragma unroll
    for (int g = 0; g < 4; g++)
        #pragma unroll
        for (int p = 0; p < PP; p++) acc[g][p] = 0ull;

    #pragma unroll 2
    for (int kb = 0; kb < 16; kb++) {
        const uint4 a4v = *(const uint4*)&At8[kb * 64 + n0];
        const u32 a4[4] = { a4v.x, a4v.y, a4v.z, a4v.w };
        #pragma unroll
        for (int j = 0; j < 4; j++) {
            const int k = 4 * kb + j;
            u64 h[PP];
            if (PP == 2) {
                const float4 hv = *(const float4*)&H[k * HS + c0];
                h[0] = pack2(hv.x, hv.y); h[1] = pack2(hv.z, hv.w);
            } else {
                const float2 hv = *(const float2*)&H[k * HS + c0];
                h[0] = pack2(hv.x, hv.y);
            }
            #pragma unroll
            for (int g = 0; g < 4; g++) {
                const float af = (float)((a4[g] >> (8 * j)) & 0xffu);
                const u64 ad = pack2dup(af);
                #pragma unroll
                for (int p = 0; p < PP; p++)
                    acc[g][p] = ffma2(ad, h[p], acc[g][p]);
            }
        }
    }
    #pragma unroll
    for (int g = 0; g < 4; g++) {
        const int n = n0 + g;
        if (PP == 2) {
            float x0, y0, x1, y1;
            unpack2(acc[g][0], x0, y0); unpack2(acc[g][1], x1, y1);
            *(float4*)&Z[n * HS + c0] = make_float4(x0, y0, x1, y1);
        } else {
            float x0, y0;
            unpack2(acc[g][0], x0, y0);
            *(float2*)&Z[n * HS + c0] = make_float2(x0, y0);
        }
    }
}

// ---- gemm (warp-local, IN-PLACE): Z[n][o] = relu(B[o] + sum_k Z[n][k]W[k][o])
// Warp w owns nodes 16w..16w+15. lane = (ni<<3)|oi: nodes n0+ni+4g, outs 4*oi.
// Weights/bias read DIRECTLY from global (L1-hot, shared by all CTAs).
template<int DIN>
__device__ __forceinline__ void gemm_frag(float* __restrict__ Zio,
                                          const float* __restrict__ W,
                                          const float* __restrict__ Bv, int t)
{
    const int warp = t >> 5, lane = t & 31;
    const int ni = lane >> 3, oi = lane & 7;
    const int n0 = warp * 16;
    const int o0 = 4 * oi;

    u64 acc[4][2];
    {
        const float4 b4 = *(const float4*)&Bv[o0];
        const u64 b01 = pack2(b4.x, b4.y), b23 = pack2(b4.z, b4.w);
        #pragma unroll
        for (int g = 0; g < 4; g++) { acc[g][0] = b01; acc[g][1] = b23; }
    }
    #pragma unroll
    for (int kb = 0; kb < DIN / 4; kb++) {
        float4 zf[4];
        #pragma unroll
        for (int g = 0; g < 4; g++)
            zf[g] = *(const float4*)&Zio[(n0 + ni + 4 * g) * HS + 4 * kb];
        #pragma unroll
        for (int j = 0; j < 4; j++) {
            const float4 wv = *(const float4*)&W[(4 * kb + j) * 32 + o0];
            const u64 w01 = pack2(wv.x, wv.y), w23 = pack2(wv.z, wv.w);
            #pragma unroll
            for (int g = 0; g < 4; g++) {
                const float a = (j == 0) ? zf[g].x : (j == 1) ? zf[g].y :
                                (j == 2) ? zf[g].z : zf[g].w;
                const u64 ad = pack2dup(a);
                acc[g][0] = ffma2(ad, w01, acc[g][0]);
                acc[g][1] = ffma2(ad, w23, acc[g][1]);
            }
        }
    }
    __syncwarp();   // all in-place reads complete before stores
    #pragma unroll
    for (int g = 0; g < 4; g++) {
        float x0, y0, x1, y1;
        unpack2(acc[g][0], x0, y0); unpack2(acc[g][1], x1, y1);
        *(float4*)&Zio[(n0 + ni + 4 * g) * HS + o0] =
            make_float4(fmaxf(x0, 0.f), fmaxf(y0, 0.f),
                        fmaxf(x1, 0.f), fmaxf(y1, 0.f));
    }
}

// ============================================================
// K1: adjacency + GIN + SortPooling -> g_pool_scratch
// ============================================================
__global__ void __launch_bounds__(128, 8)
gin_kernel(
    const int* __restrict__ labels,
    const int* __restrict__ src,
    const int* __restrict__ dst,
    const float* __restrict__ emb,
    const float* __restrict__ w1_0, const float* __restrict__ b1_0,
    const float* __restrict__ w2_0, const float* __restrict__ b2_0,
    const float* __restrict__ w1_1, const float* __restrict__ b1_1,
    const float* __restrict__ w2_1, const float* __restrict__ b2_1,
    const float* __restrict__ w1_2, const float* __restrict__ b1_2,
    const float* __restrict__ w2_2, const float* __restrict__ b2_2)
{
    __shared__ __align__(16) float pool[5632];
    __shared__ int nor[10];

    u32*   At8 = (u32*)pool;
    float* H0  = pool + P_H0;
    float* H1  = pool + P_H1;

    const int g = blockIdx.x;
    const int t = threadIdx.x;

    // ---- zero packed adjacency ----
    {
        const uint4 z4 = make_uint4(0u, 0u, 0u, 0u);
        *(uint4*)(At8 + t * 4)         = z4;
        *(uint4*)(At8 + (t + 128) * 4) = z4;
    }
    __syncthreads();

    // ---- edges + diagonal into byte-packed At8; embedding load ----
    {
        const int4* s4p = (const int4*)(src + ((long)g << 10));
        const int4* d4p = (const int4*)(dst + ((long)g << 10));
        #pragma unroll
        for (int i = 0; i < 2; i++) {
            const int4 s = s4p[t + i * 128];
            const int4 d = d4p[t + i * 128];
            const int sx = s.x & 63, sy = s.y & 63, sz = s.z & 63, sw = s.w & 63;
            atomicAdd(&At8[(sx >> 2) * 64 + (d.x & 63)], 1u << (8 * (sx & 3)));
            atomicAdd(&At8[(sy >> 2) * 64 + (d.y & 63)], 1u << (8 * (sy & 3)));
            atomicAdd(&At8[(sz >> 2) * 64 + (d.z & 63)], 1u << (8 * (sz & 3)));
            atomicAdd(&At8[(sw >> 2) * 64 + (d.w & 63)], 1u << (8 * (sw & 3)));
        }
        if (t < 64) atomicAdd(&At8[(t >> 2) * 64 + t], 1u << (8 * (t & 3)));
    }
    {
        const int n = t >> 1, c0 = (t & 1) * 8;
        const float4 v0 = *(const float4*)(emb + labels[(g << 6) + n] * 16 + c0);
        const float4 v1 = *(const float4*)(emb + labels[(g << 6) + n] * 16 + c0 + 4);
        *(float4*)(H0 + n * HS + c0)     = v0;
        *(float4*)(H0 + n * HS + c0 + 4) = v1;
    }
    __syncthreads();

    // ---- layer 0: H0 -> H1 (agg), then in-place gemms on H1 ----
    agg_frag<16>(At8, H0, H1, t);
    __syncwarp();
    gemm_frag<16>(H1, w1_0, b1_0, t);
    __syncwarp();
    gemm_frag<32>(H1, w2_0, b2_0, t);
    __syncthreads();

    // ---- layer 1: H1 -> H0 ----
    agg_frag<32>(At8, H1, H0, t);
    __syncwarp();
    gemm_frag<32>(H0, w1_1, b1_1, t);
    __syncwarp();
    gemm_frag<32>(H0, w2_1, b2_1, t);
    __syncthreads();

    // ---- layer 2: H0 -> H1 ----
    agg_frag<32>(At8, H0, H1, t);
    __syncwarp();
    gemm_frag<32>(H1, w1_2, b1_2, t);
    __syncwarp();
    gemm_frag<32>(H1, w2_2, b2_2, t);
    __syncthreads();

    float* cur = H1;

    // ---- SortPooling: stable rank by channel 31 desc, keep 10 ----
    if (t < 64) {
        const float key = cur[t * HS + 31];
        int r = 0;
        for (int m = 0; m < 64; m++) {
            const float km = cur[m * HS + 31];
            r += (km > key) || (km == key && m < t);
        }
        if (r < 10) nor[r] = t;
    }
    __syncthreads();

    // ---- write pooled features [ci][r] to global scratch (coalesced) ----
    for (int idx = t; idx < 320; idx += 128) {
        const int ci = idx / 10, r = idx - ci * 10;
        g_pool_scratch[(long)g * 320 + idx] = cur[nor[r] * HS + ci];
    }
}

// ============================================================
// K2: conv1 + maxpool + conv2 + mean + scorer; warp-per-graph
// minBlocks 3 -> 4: smem 53.9KB x4 = 215.5KB < 227KB, regs 56 x 1024 < 64K.
// ============================================================
#define C1W 0       // 160 x 33 = 5280 (transposed [ci*5+k][co])
#define C1B 5280    // 32
#define C2W 5312    // 160 x 17 = 2720 (transposed)
#define C2B 8032    // 16
#define SW1 8048    // 256
#define SB1 8304    // 16
#define SW2 8320    // 16
#define SB2 8336    // 1
#define PS  8352    // 8 x 384
#define YB  11424   // 8 x 256
#define K2_SMEM 13472

__global__ void __launch_bounds__(256, 4)
conv_kernel(
    const float* __restrict__ conv1_w, const float* __restrict__ conv1_b,
    const float* __restrict__ conv2_w, const float* __restrict__ conv2_b,
    const float* __restrict__ sc_w1, const float* __restrict__ sc_b1,
    const float* __restrict__ sc_w2, const float* __restrict__ sc_b2,
    float* __restrict__ out, int B)
{
    extern __shared__ __align__(16) float s[];
    const int t = threadIdx.x;
    const int w = t >> 5, lane = t & 31;

    // ---- stage all weights once per CTA (8 graphs), transposed ----
    for (int idx = t; idx < 5120; idx += 256) {
        const int co = idx / 160, r = idx - co * 160;
        s[C1W + r * 33 + co] = conv1_w[idx];
    }
    for (int idx = t; idx < 2560; idx += 256) {
        const int co = idx / 160, r = idx - co * 160;
        s[C2W + r * 17 + co] = conv2_w[idx];
    }
    if (t < 32)              s[C1B + t] = conv1_b[t];
    if (t >= 32 && t < 48)   s[C2B + (t - 32)] = conv2_b[t - 32];
    if (t >= 48 && t < 64)   s[SB1 + (t - 48)] = sc_b1[t - 48];
    s[SW1 + t] = sc_w1[t];
    if (t >= 224 && t < 240) s[SW2 + (t - 224)] = sc_w2[t - 224];
    if (t == 255)            s[SB2] = sc_b2[0];
    __syncthreads();

    const int g = blockIdx.x * 8 + w;
    if (g >= B) return;

    float* ps = s + PS + w * 384;   // pooledT [ci*12 + r], r<10 valid
    float* yb = s + YB + w * 256;   // ybufT   [ci*8 + q],  q<5 valid

    // ---- load pooled features (coalesced) into padded smem ----
    for (int i = lane; i < 384; i += 32) ps[i] = 0.f;
    __syncwarp();
    for (int i = lane; i < 320; i += 32) {
        const int ci = i / 10, r = i - ci * 10;
        ps[ci * 12 + r] = g_pool_scratch[(long)g * 320 + i];
    }
    __syncwarp();

    // ---- conv1 (lane = co), f32x2 over position pairs ----
    {
        u64 A0 = 0, A1 = 0, A2 = 0, A3 = 0, A4 = 0;
        #pragma unroll 2
        for (int ci = 0; ci < 32; ci++) {
            const int wr = C1W + ci * 5 * 33 + lane;
            const float w0 = s[wr], w1 = s[wr + 33], w2 = s[wr + 66],
                        w3 = s[wr + 99], w4 = s[wr + 132];
            const float4 va = *(const float4*)&ps[ci * 12];
            const float4 vb = *(const float4*)&ps[ci * 12 + 4];
            const float4 vc = *(const float4*)&ps[ci * 12 + 8];
            const u64 E1 = pack2(va.x, va.y), E2 = pack2(va.z, va.w);
            const u64 E3 = pack2(vb.x, vb.y), E4 = pack2(vb.z, vb.w);
            const u64 E5 = pack2(vc.x, vc.y);
            const u64 O0 = pack2(0.f, va.x),  O1 = pack2(va.y, va.z);
            const u64 O2 = pack2(va.w, vb.x), O3 = pack2(vb.y, vb.z);
            const u64 O4 = pack2(vb.w, vc.x), O5 = pack2(vc.y, vc.z);
            const u64 d0 = pack2dup(w0), d1 = pack2dup(w1), d2 = pack2dup(w2),
                      d3 = pack2dup(w3), d4 = pack2dup(w4);
            A1 = ffma2(d0, E1, A1); A2 = ffma2(d0, E2, A2);
            A3 = ffma2(d0, E3, A3); A4 = ffma2(d0, E4, A4);
            A0 = ffma2(d1, O0, A0); A1 = ffma2(d1, O1, A1);
            A2 = ffma2(d1, O2, A2); A3 = ffma2(d1, O3, A3);
            A4 = ffma2(d1, O4, A4);
            A0 = ffma2(d2, E1, A0); A1 = ffma2(d2, E2, A1);
            A2 = ffma2(d2, E3, A2); A3 = ffma2(d2, E4, A3);
            A4 = ffma2(d2, E5, A4);
            A0 = ffma2(d3, O1, A0); A1 = ffma2(d3, O2, A1);
            A2 = ffma2(d3, O3, A2); A3 = ffma2(d3, O4, A3);
            A4 = ffma2(d3, O5, A4);
            A0 = ffma2(d4, E2, A0); A1 = ffma2(d4, E3, A1);
            A2 = ffma2(d4, E4, A2); A3 = ffma2(d4, E5, A3);
        }
        const float b = s[C1B + lane];
        float o0, o1;
        unpack2(A0, o0, o1);
        yb[lane * 8 + 0] = fmaxf(fmaxf(o0 + b, 0.f), fmaxf(o1 + b, 0.f));
        unpack2(A1, o0, o1);
        yb[lane * 8 + 1] = fmaxf(fmaxf(o0 + b, 0.f), fmaxf(o1 + b, 0.f));
        unpack2(A2, o0, o1);
        yb[lane * 8 + 2] = fmaxf(fmaxf(o0 + b, 0.f), fmaxf(o1 + b, 0.f));
        unpack2(A3, o0, o1);
        yb[lane * 8 + 3] = fmaxf(fmaxf(o0 + b, 0.f), fmaxf(o1 + b, 0.f));
        unpack2(A4, o0, o1);
        yb[lane * 8 + 4] = fmaxf(fmaxf(o0 + b, 0.f), fmaxf(o1 + b, 0.f));
        yb[lane * 8 + 5] = 0.f;
        yb[lane * 8 + 6] = 0.f;
        yb[lane * 8 + 7] = 0.f;
    }
    __syncwarp();

    // ---- conv2: full warp; co = lane&15, ci-half = lane>>4 ----
    float feat = 0.f;
    {
        const int co = lane & 15;
        const int cib = (lane >> 4) * 16;
        float a2[5];
        #pragma unroll
        for (int p = 0; p < 5; p++) a2[p] = 0.f;
        #pragma unroll 2
        for (int ci = cib; ci < cib + 16; ci++) {
            const int wr = C2W + ci * 5 * 17 + co;
            float w5[5];
            #pragma unroll
            for (int k = 0; k < 5; k++) w5[k] = s[wr + k * 17];
            const float4 ya = *(const float4*)&yb[ci * 8];
            const float y4 = yb[ci * 8 + 4];
            const float a[9] = { 0.f, 0.f, ya.x, ya.y, ya.z, ya.w, y4, 0.f, 0.f };
            #pragma unroll
            for (int p = 0; p < 5; p++)
                #pragma unroll
                for (int k = 0; k < 5; k++)
                    a2[p] = fmaf(w5[k], a[p + k], a2[p]);
        }
        #pragma unroll
        for (int p = 0; p < 5; p++)
            a2[p] += __shfl_down_sync(0xffffffffu, a2[p], 16);
        if (lane < 16) {
            const float b = s[C2B + co];
            float sum = 0.f;
            #pragma unroll
            for (int p = 0; p < 5; p++) sum += fmaxf(a2[p] + b, 0.f);
            feat = 0.2f * sum;
        }
    }

    // ---- scorer MLP via shuffles (feat valid in lanes 0..15) ----
    {
        const int o = lane & 15;
        float a = s[SB1 + o];
        #pragma unroll
        for (int i = 0; i < 16; i++)
            a = fmaf(__shfl_sync(0xffffffffu, feat, i), s[SW1 + i * 16 + o], a);
        float hid = fmaxf(a, 0.f) * s[SW2 + o];
        if (lane >= 16) hid = 0.f;
        #pragma unroll
        for (int off = 16; off; off >>= 1)
            hid += __shfl_down_sync(0xffffffffu, hid, off);
        if (lane == 0) out[g] = hid + s[SB2];
    }
}

extern "C" void kernel_launch(void* const* d_in, const int* in_sizes, int n_in,
                              void* d_out, int out_size)
{
    const int B = in_sizes[0] / 64;

    gin_kernel<<<B, 128>>>(
        (const int*)d_in[0], (const int*)d_in[1], (const int*)d_in[2],
        (const float*)d_in[3],
        (const float*)d_in[4],  (const float*)d_in[5],
        (const float*)d_in[6],  (const float*)d_in[7],
        (const float*)d_in[8],  (const float*)d_in[9],
        (const float*)d_in[10], (const float*)d_in[11],
        (const float*)d_in[12], (const float*)d_in[13],
        (const float*)d_in[14], (const float*)d_in[15]);

    const int smem = K2_SMEM * sizeof(float);   // 53888 B
    cudaFuncSetAttribute(conv_kernel,
                         cudaFuncAttributeMaxDynamicSharedMemorySize, smem);
    conv_kernel<<<(B + 7) / 8, 256, smem>>>(
        (const float*)d_in[16], (const float*)d_in[17],
        (const float*)d_in[18], (const float*)d_in[19],
        (const float*)d_in[20], (const float*)d_in[21],
        (const float*)d_in[22], (const float*)d_in[23],
        (float*)d_out, B);
}

// round 17
// speedup vs baseline: 1.0157x; 1.0157x over previous
#include <cuda_runtime.h>

typedef unsigned long long u64;
typedef unsigned int u32;

__device__ __forceinline__ u64 pack2(float x, float y) {
    u64 r; asm("mov.b64 %0, {%1, %2};" : "=l"(r) : "f"(x), "f"(y)); return r;
}
__device__ __forceinline__ u64 pack2dup(float x) {
    u64 r; asm("mov.b64 %0, {%1, %1};" : "=l"(r) : "f"(x)); return r;
}
__device__ __forceinline__ void unpack2(u64 v, float& x, float& y) {
    asm("mov.b64 {%0, %1}, %2;" : "=f"(x), "=f"(y) : "l"(v));
}
__device__ __forceinline__ u64 ffma2(u64 a, u64 b, u64 c) {
    u64 d; asm("fma.rn.f32x2 %0, %1, %2, %3;" : "=l"(d) : "l"(a), "l"(b), "l"(c));
    return d;
}

#define HS 36   // H row stride (16B-aligned rows)

// K1 pool layout (floats), 5632 total:
//  At8 (1024 u32) @0 | H0 @1024..3328 | H1 @3328..5632
#define P_H0   1024
#define P_H1   3328

#define MAXB 4096
__device__ float g_pool_scratch[MAXB * 320];   // [g][ci*10 + r]
__device__ float g_c1wT[160 * 32];             // [(ci*5+k)*32 + co]
__device__ float g_c2wT[160 * 16];             // [(ci*5+k)*16 + co]

// ============================================================
// pack: transpose conv weights into lane-coalesced global layout
// ============================================================
__global__ void pack_kernel(const float* __restrict__ conv1_w,
                            const float* __restrict__ conv2_w)
{
    const int i = blockIdx.x * blockDim.x + threadIdx.x;
    if (i < 5120) {
        const int co = i / 160, r = i - co * 160;
        g_c1wT[r * 32 + co] = conv1_w[i];
    }
    if (i < 2560) {
        const int co = i / 160, r = i - co * 160;
        g_c2wT[r * 16 + co] = conv2_w[i];
    }
}

// ---- agg: Z[n][c] = sum_k A[n][k]*H[k][c]; A byte-packed (incl. diag) ----
template<int W>
__device__ __forceinline__ void agg_frag(const u32* __restrict__ At8,
                                         const float* __restrict__ H,
                                         float* __restrict__ Z, int t)
{
    constexpr int PP = W / 16;
    const int warp = t >> 5, lane = t & 31;
    const int ni = lane >> 3, ci = lane & 7;
    const int n0 = warp * 16 + 4 * ni;
    const int c0 = ci * 2 * PP;

    u64 acc[4][PP];
    #pragma unroll
    for (int g = 0; g < 4; g++)
        #pragma unroll
        for (int p = 0; p < PP; p++) acc[g][p] = 0ull;

    #pragma unroll 2
    for (int kb = 0; kb < 16; kb++) {
        const uint4 a4v = *(const uint4*)&At8[kb * 64 + n0];
        const u32 a4[4] = { a4v.x, a4v.y, a4v.z, a4v.w };
        #pragma unroll
        for (int j = 0; j < 4; j++) {
            const int k = 4 * kb + j;
            u64 h[PP];
            if (PP == 2) {
                const float4 hv = *(const float4*)&H[k * HS + c0];
                h[0] = pack2(hv.x, hv.y); h[1] = pack2(hv.z, hv.w);
            } else {
                const float2 hv = *(const float2*)&H[k * HS + c0];
                h[0] = pack2(hv.x, hv.y);
            }
            #pragma unroll
            for (int g = 0; g < 4; g++) {
                const float af = (float)((a4[g] >> (8 * j)) & 0xffu);
                const u64 ad = pack2dup(af);
                #pragma unroll
                for (int p = 0; p < PP; p++)
                    acc[g][p] = ffma2(ad, h[p], acc[g][p]);
            }
        }
    }
    #pragma unroll
    for (int g = 0; g < 4; g++) {
        const int n = n0 + g;
        if (PP == 2) {
            float x0, y0, x1, y1;
            unpack2(acc[g][0], x0, y0); unpack2(acc[g][1], x1, y1);
            *(float4*)&Z[n * HS + c0] = make_float4(x0, y0, x1, y1);
        } else {
            float x0, y0;
            unpack2(acc[g][0], x0, y0);
            *(float2*)&Z[n * HS + c0] = make_float2(x0, y0);
        }
    }
}

// ---- gemm (warp-local, in-place); weights direct from global ----
template<int DIN>
__device__ __forceinline__ void gemm_frag(float* __restrict__ Zio,
                                          const float* __restrict__ W,
                                          const float* __restrict__ Bv, int t)
{
    const int warp = t >> 5, lane = t & 31;
    const int ni = lane >> 3, oi = lane & 7;
    const int n0 = warp * 16;
    const int o0 = 4 * oi;

    u64 acc[4][2];
    {
        const float4 b4 = *(const float4*)&Bv[o0];
        const u64 b01 = pack2(b4.x, b4.y), b23 = pack2(b4.z, b4.w);
        #pragma unroll
        for (int g = 0; g < 4; g++) { acc[g][0] = b01; acc[g][1] = b23; }
    }
    #pragma unroll
    for (int kb = 0; kb < DIN / 4; kb++) {
        float4 zf[4];
        #pragma unroll
        for (int g = 0; g < 4; g++)
            zf[g] = *(const float4*)&Zio[(n0 + ni + 4 * g) * HS + 4 * kb];
        #pragma unroll
        for (int j = 0; j < 4; j++) {
            const float4 wv = *(const float4*)&W[(4 * kb + j) * 32 + o0];
            const u64 w01 = pack2(wv.x, wv.y), w23 = pack2(wv.z, wv.w);
            #pragma unroll
            for (int g = 0; g < 4; g++) {
                const float a = (j == 0) ? zf[g].x : (j == 1) ? zf[g].y :
                                (j == 2) ? zf[g].z : zf[g].w;
                const u64 ad = pack2dup(a);
                acc[g][0] = ffma2(ad, w01, acc[g][0]);
                acc[g][1] = ffma2(ad, w23, acc[g][1]);
            }
        }
    }
    __syncwarp();
    #pragma unroll
    for (int g = 0; g < 4; g++) {
        float x0, y0, x1, y1;
        unpack2(acc[g][0], x0, y0); unpack2(acc[g][1], x1, y1);
        *(float4*)&Zio[(n0 + ni + 4 * g) * HS + o0] =
            make_float4(fmaxf(x0, 0.f), fmaxf(y0, 0.f),
                        fmaxf(x1, 0.f), fmaxf(y1, 0.f));
    }
}

// ============================================================
// K1: adjacency + GIN + SortPooling -> g_pool_scratch
// ============================================================
__global__ void __launch_bounds__(128, 8)
gin_kernel(
    const int* __restrict__ labels,
    const int* __restrict__ src,
    const int* __restrict__ dst,
    const float* __restrict__ emb,
    const float* __restrict__ w1_0, const float* __restrict__ b1_0,
    const float* __restrict__ w2_0, const float* __restrict__ b2_0,
    const float* __restrict__ w1_1, const float* __restrict__ b1_1,
    const float* __restrict__ w2_1, const float* __restrict__ b2_1,
    const float* __restrict__ w1_2, const float* __restrict__ b1_2,
    const float* __restrict__ w2_2, const float* __restrict__ b2_2)
{
    __shared__ __align__(16) float pool[5632];
    __shared__ int nor[10];

    u32*   At8 = (u32*)pool;
    float* H0  = pool + P_H0;
    float* H1  = pool + P_H1;

    const int g = blockIdx.x;
    const int t = threadIdx.x;

    {
        const uint4 z4 = make_uint4(0u, 0u, 0u, 0u);
        *(uint4*)(At8 + t * 4)         = z4;
        *(uint4*)(At8 + (t + 128) * 4) = z4;
    }
    __syncthreads();

    {
        const int4* s4p = (const int4*)(src + ((long)g << 10));
        const int4* d4p = (const int4*)(dst + ((long)g << 10));
        #pragma unroll
        for (int i = 0; i < 2; i++) {
            const int4 s = s4p[t + i * 128];
            const int4 d = d4p[t + i * 128];
            const int sx = s.x & 63, sy = s.y & 63, sz = s.z & 63, sw = s.w & 63;
            atomicAdd(&At8[(sx >> 2) * 64 + (d.x & 63)], 1u << (8 * (sx & 3)));
            atomicAdd(&At8[(sy >> 2) * 64 + (d.y & 63)], 1u << (8 * (sy & 3)));
            atomicAdd(&At8[(sz >> 2) * 64 + (d.z & 63)], 1u << (8 * (sz & 3)));
            atomicAdd(&At8[(sw >> 2) * 64 + (d.w & 63)], 1u << (8 * (sw & 3)));
        }
        if (t < 64) atomicAdd(&At8[(t >> 2) * 64 + t], 1u << (8 * (t & 3)));
    }
    {
        const int n = t >> 1, c0 = (t & 1) * 8;
        const float4 v0 = *(const float4*)(emb + labels[(g << 6) + n] * 16 + c0);
        const float4 v1 = *(const float4*)(emb + labels[(g << 6) + n] * 16 + c0 + 4);
        *(float4*)(H0 + n * HS + c0)     = v0;
        *(float4*)(H0 + n * HS + c0 + 4) = v1;
    }
    __syncthreads();

    agg_frag<16>(At8, H0, H1, t);
    __syncwarp();
    gemm_frag<16>(H1, w1_0, b1_0, t);
    __syncwarp();
    gemm_frag<32>(H1, w2_0, b2_0, t);
    __syncthreads();

    agg_frag<32>(At8, H1, H0, t);
    __syncwarp();
    gemm_frag<32>(H0, w1_1, b1_1, t);
    __syncwarp();
    gemm_frag<32>(H0, w2_1, b2_1, t);
    __syncthreads();

    agg_frag<32>(At8, H0, H1, t);
    __syncwarp();
    gemm_frag<32>(H1, w1_2, b1_2, t);
    __syncwarp();
    gemm_frag<32>(H1, w2_2, b2_2, t);
    __syncthreads();

    float* cur = H1;

    if (t < 64) {
        const float key = cur[t * HS + 31];
        int r = 0;
        for (int m = 0; m < 64; m++) {
            const float km = cur[m * HS + 31];
            r += (km > key) || (km == key && m < t);
        }
        if (r < 10) nor[r] = t;
    }
    __syncthreads();

    for (int idx = t; idx < 320; idx += 128) {
        const int ci = idx / 10, r = idx - ci * 10;
        g_pool_scratch[(long)g * 320 + idx] = cur[nor[r] * HS + ci];
    }
}

// ============================================================
// K2: conv1 + maxpool + conv2 + mean + scorer; warp-per-graph
// NO weight smem: conv weights from transposed global (L1-hot).
// smem = per-warp activations only (20.5 KB static) -> reg-limited occ.
// ============================================================
__global__ void __launch_bounds__(256, 4)
conv_kernel(
    const float* __restrict__ conv1_b,
    const float* __restrict__ conv2_b,
    const float* __restrict__ sc_w1, const float* __restrict__ sc_b1,
    const float* __restrict__ sc_w2, const float* __restrict__ sc_b2,
    float* __restrict__ out, int B)
{
    __shared__ __align__(16) float sps[8 * 384];   // pooledT [w][ci*12 + r]
    __shared__ __align__(16) float syb[8 * 256];   // ybufT   [w][ci*8 + q]

    const int t = threadIdx.x;
    const int w = t >> 5, lane = t & 31;

    const int g = blockIdx.x * 8 + w;
    if (g >= B) return;

    float* ps = sps + w * 384;
    float* yb = syb + w * 256;

    // ---- load pooled features (coalesced) into padded smem ----
    for (int i = lane; i < 384; i += 32) ps[i] = 0.f;
    __syncwarp();
    for (int i = lane; i < 320; i += 32) {
        const int ci = i / 10, r = i - ci * 10;
        ps[ci * 12 + r] = g_pool_scratch[(long)g * 320 + i];
    }
    __syncwarp();

    // ---- conv1 (lane = co), f32x2; weights via lane-coalesced LDG ----
    {
        u64 A0 = 0, A1 = 0, A2 = 0, A3 = 0, A4 = 0;
        #pragma unroll 2
        for (int ci = 0; ci < 32; ci++) {
            const float* wp = g_c1wT + ci * 5 * 32 + lane;
            const float w0 = __ldg(wp), w1 = __ldg(wp + 32), w2 = __ldg(wp + 64),
                        w3 = __ldg(wp + 96), w4 = __ldg(wp + 128);
            const float4 va = *(const float4*)&ps[ci * 12];
            const float4 vb = *(const float4*)&ps[ci * 12 + 4];
            const float4 vc = *(const float4*)&ps[ci * 12 + 8];
            const u64 E1 = pack2(va.x, va.y), E2 = pack2(va.z, va.w);
            const u64 E3 = pack2(vb.x, vb.y), E4 = pack2(vb.z, vb.w);
            const u64 E5 = pack2(vc.x, vc.y);
            const u64 O0 = pack2(0.f, va.x),  O1 = pack2(va.y, va.z);
            const u64 O2 = pack2(va.w, vb.x), O3 = pack2(vb.y, vb.z);
            const u64 O4 = pack2(vb.w, vc.x), O5 = pack2(vc.y, vc.z);
            const u64 d0 = pack2dup(w0), d1 = pack2dup(w1), d2 = pack2dup(w2),
                      d3 = pack2dup(w3), d4 = pack2dup(w4);
            A1 = ffma2(d0, E1, A1); A2 = ffma2(d0, E2, A2);
            A3 = ffma2(d0, E3, A3); A4 = ffma2(d0, E4, A4);
            A0 = ffma2(d1, O0, A0); A1 = ffma2(d1, O1, A1);
            A2 = ffma2(d1, O2, A2); A3 = ffma2(d1, O3, A3);
            A4 = ffma2(d1, O4, A4);
            A0 = ffma2(d2, E1, A0); A1 = ffma2(d2, E2, A1);
            A2 = ffma2(d2, E3, A2); A3 = ffma2(d2, E4, A3);
            A4 = ffma2(d2, E5, A4);
            A0 = ffma2(d3, O1, A0); A1 = ffma2(d3, O2, A1);
            A2 = ffma2(d3, O3, A2); A3 = ffma2(d3, O4, A3);
            A4 = ffma2(d3, O5, A4);
            A0 = ffma2(d4, E2, A0); A1 = ffma2(d4, E3, A1);
            A2 = ffma2(d4, E4, A2); A3 = ffma2(d4, E5, A3);
        }
        const float b = __ldg(conv1_b + lane);
        float o0, o1;
        unpack2(A0, o0, o1);
        yb[lane * 8 + 0] = fmaxf(fmaxf(o0 + b, 0.f), fmaxf(o1 + b, 0.f));
        unpack2(A1, o0, o1);
        yb[lane * 8 + 1] = fmaxf(fmaxf(o0 + b, 0.f), fmaxf(o1 + b, 0.f));
        unpack2(A2, o0, o1);
        yb[lane * 8 + 2] = fmaxf(fmaxf(o0 + b, 0.f), fmaxf(o1 + b, 0.f));
        unpack2(A3, o0, o1);
        yb[lane * 8 + 3] = fmaxf(fmaxf(o0 + b, 0.f), fmaxf(o1 + b, 0.f));
        unpack2(A4, o0, o1);
        yb[lane * 8 + 4] = fmaxf(fmaxf(o0 + b, 0.f), fmaxf(o1 + b, 0.f));
        yb[lane * 8 + 5] = 0.f;
        yb[lane * 8 + 6] = 0.f;
        yb[lane * 8 + 7] = 0.f;
    }
    __syncwarp();

    // ---- conv2: full warp; co = lane&15, ci-half = lane>>4 ----
    float feat = 0.f;
    {
        const int co = lane & 15;
        const int cib = (lane >> 4) * 16;
        float a2[5];
        #pragma unroll
        for (int p = 0; p < 5; p++) a2[p] = 0.f;
        #pragma unroll 2
        for (int ci = cib; ci < cib + 16; ci++) {
            const float* wp = g_c2wT + ci * 5 * 16 + co;
            float w5[5];
            #pragma unroll
            for (int k = 0; k < 5; k++) w5[k] = __ldg(wp + k * 16);
            const float4 ya = *(const float4*)&yb[ci * 8];
            const float y4 = yb[ci * 8 + 4];
            const float a[9] = { 0.f, 0.f, ya.x, ya.y, ya.z, ya.w, y4, 0.f, 0.f };
            #pragma unroll
            for (int p = 0; p < 5; p++)
                #pragma unroll
                for (int k = 0; k < 5; k++)
                    a2[p] = fmaf(w5[k], a[p + k], a2[p]);
        }
        #pragma unroll
        for (int p = 0; p < 5; p++)
            a2[p] += __shfl_down_sync(0xffffffffu, a2[p], 16);
        if (lane < 16) {
            const float b = __ldg(conv2_b + co);
            float sum = 0.f;
            #pragma unroll
            for (int p = 0; p < 5; p++) sum += fmaxf(a2[p] + b, 0.f);
            feat = 0.2f * sum;
        }
    }

    // ---- scorer MLP via shuffles; weights from global (L1-hot) ----
    {
        const int o = lane & 15;
        float a = __ldg(sc_b1 + o);
        #pragma unroll
        for (int i = 0; i < 16; i++)
            a = fmaf(__shfl_sync(0xffffffffu, feat, i), __ldg(sc_w1 + i * 16 + o), a);
        float hid = fmaxf(a, 0.f) * __ldg(sc_w2 + o);
        if (lane >= 16) hid = 0.f;
        #pragma unroll
        for (int off = 16; off; off >>= 1)
            hid += __shfl_down_sync(0xffffffffu, hid, off);
        if (lane == 0) out[g] = hid + __ldg(sc_b2);
    }
}

extern "C" void kernel_launch(void* const* d_in, const int* in_sizes, int n_in,
                              void* d_out, int out_size)
{
    const int B = in_sizes[0] / 64;

    pack_kernel<<<20, 256>>>((const float*)d_in[16], (const float*)d_in[18]);

    gin_kernel<<<B, 128>>>(
        (const int*)d_in[0], (const int*)d_in[1], (const int*)d_in[2],
        (const float*)d_in[3],
        (const float*)d_in[4],  (const float*)d_in[5],
        (const float*)d_in[6],  (const float*)d_in[7],
        (const float*)d_in[8],  (const float*)d_in[9],
        (const float*)d_in[10], (const float*)d_in[11],
        (const float*)d_in[12], (const float*)d_in[13],
        (const float*)d_in[14], (const float*)d_in[15]);

    conv_kernel<<<(B + 7) / 8, 256>>>(
        (const float*)d_in[17], (const float*)d_in[19],
        (const float*)d_in[20], (const float*)d_in[21],
        (const float*)d_in[22], (const float*)d_in[23],
        (float*)d_out, B);
}